// round 13
// baseline (speedup 1.0000x reference)
#include <cuda_runtime.h>
#include <cuda_fp16.h>
#include <math.h>
#include <stdint.h>

#define S_LEN 4096
#define DIM   3072
#define HEADS 24
#define HD    128
#define MH    9216
#define FOUT  27648      // 3*DIM + 2*MH
#define QKV   9216       // 3*DIM
#define CATK  12288      // DIM + MH
#define EPS   1e-6f

// ---------------- scratch (device globals; no allocations allowed) ----------
__device__ __half g_h   [(size_t)S_LEN * DIM];
__device__ __half g_P   [(size_t)S_LEN * FOUT];
__device__ __half g_Qb  [(size_t)HEADS * S_LEN * HD];   // [h][s][d], pre-scaled
__device__ __half g_Kb  [(size_t)HEADS * S_LEN * HD];   // [h][s][d]
__device__ __half g_Vt  [(size_t)DIM * S_LEN];          // [h*HD+d][s]
__device__ __half g_cat [(size_t)S_LEN * CATK];         // [attn | swiglu]
__device__ __half g_w1h [(size_t)FOUT * DIM];           // w1^T [FOUT][DIM]
__device__ __half g_woh [(size_t)DIM * CATK];           // [wo_attn;wo_mlp]^T

__device__ __forceinline__ void cp16(uint32_t s, const void* g) {
    asm volatile("cp.async.cg.shared.global [%0], [%1], 16;\n" :: "r"(s), "l"(g));
}
__device__ __forceinline__ void mma_f16(float c[4],
    uint32_t a0, uint32_t a1, uint32_t a2, uint32_t a3, uint32_t b0, uint32_t b1)
{
    asm volatile(
        "mma.sync.aligned.m16n8k16.row.col.f32.f16.f16.f32 "
        "{%0,%1,%2,%3},{%4,%5,%6,%7},{%8,%9},{%0,%1,%2,%3};"
        : "+f"(c[0]), "+f"(c[1]), "+f"(c[2]), "+f"(c[3])
        : "r"(a0), "r"(a1), "r"(a2), "r"(a3), "r"(b0), "r"(b1));
}
__device__ __forceinline__ void ldsm4(uint32_t r[4], uint32_t addr) {
    asm volatile("ldmatrix.sync.aligned.m8n8.x4.shared.b16 {%0,%1,%2,%3}, [%4];"
                 : "=r"(r[0]), "=r"(r[1]), "=r"(r[2]), "=r"(r[3]) : "r"(addr));
}

// ---------------- kernel 0: fp32 [K][N] -> half [N][outK] transpose ----------
__global__ __launch_bounds__(256) void k_cvtT(
    const float* __restrict__ in, __half* __restrict__ out,
    int K, int N, int outK, int kofs)
{
    __shared__ float t[32][33];
    int k0 = blockIdx.y * 32, n0 = blockIdx.x * 32;
    int tx = threadIdx.x & 31, ty = threadIdx.x >> 5;
    #pragma unroll
    for (int i = 0; i < 32; i += 8)
        t[ty + i][tx] = in[(size_t)(k0 + ty + i) * N + n0 + tx];
    __syncthreads();
    #pragma unroll
    for (int i = 0; i < 32; i += 8)
        out[(size_t)(n0 + ty + i) * outK + kofs + k0 + tx] = __float2half_rn(t[tx][ty + i]);
}

// ---------------- kernel 1: LayerNorm + modulation (-> half) -----------------
__global__ __launch_bounds__(256) void k_lnmod(
    const float* __restrict__ x, const float* __restrict__ temb,
    __half* __restrict__ h)
{
    int s = blockIdx.x;
    const float* xr = x + (size_t)s * DIM;
    float v[12];
    float lsum = 0.f, lsq = 0.f;
    #pragma unroll
    for (int i = 0; i < 12; i++) {
        float t = xr[threadIdx.x + i * 256];
        v[i] = t; lsum += t; lsq += t * t;
    }
    __shared__ float red[16];
    #pragma unroll
    for (int o = 16; o; o >>= 1) {
        lsum += __shfl_xor_sync(0xffffffffu, lsum, o);
        lsq  += __shfl_xor_sync(0xffffffffu, lsq,  o);
    }
    int w = threadIdx.x >> 5;
    if ((threadIdx.x & 31) == 0) { red[w] = lsum; red[8 + w] = lsq; }
    __syncthreads();
    float ssum = 0.f, ssq = 0.f;
    #pragma unroll
    for (int i = 0; i < 8; i++) { ssum += red[i]; ssq += red[8 + i]; }
    float mu  = ssum * (1.0f / DIM);
    float var = ssq * (1.0f / DIM) - mu * mu;
    float rs  = rsqrtf(var + EPS);
    __half* hr = h + (size_t)s * DIM;
    #pragma unroll
    for (int i = 0; i < 12; i++) {
        int d = threadIdx.x + i * 256;
        float sc = temb[DIM + d];
        float sh = temb[d];
        hr[d] = __float2half_rn((v[i] - mu) * rs * (1.f + sc) + sh);
    }
}

// ---------------- kernel 2: fp16 GEMM (ldmatrix), 256x128 CTA, 512 thr ------
// 16 warps in 4m x 4n grid; per-warp 64x32 tile (identical fragment layout to
// the verified 2-CTA version; only base addresses changed).
#define MM5_STG 4
#define A5_B  20480                      // 256 rows * 80 B
#define B5_B  10240                      // 128 rows * 80 B
#define ST5B  (A5_B + B5_B)              // 30720 B per stage
#define MM_SMEM5 (MM5_STG * ST5B)        // 122880 B

template <bool FINAL, typename OutT>
__global__ __launch_bounds__(512, 1) void k_mm5(
    const __half* __restrict__ A, const __half* __restrict__ B,
    OutT* __restrict__ C, int M, int N, int K, int tiles_m, int tiles_n,
    const float* __restrict__ xres, const float* __restrict__ temb)
{
    extern __shared__ float smf[];

    // block swizzle (GROUP_M = 16 m-tiles per band)
    int pid = blockIdx.x;
    const int GROUPM = 16;
    int npg     = GROUPM * tiles_n;
    int groupid = pid / npg;
    int firstm  = groupid * GROUPM;
    int gsz     = min(GROUPM, tiles_m - firstm);
    int pm      = firstm + (pid % npg) % gsz;
    int pn      = (pid % npg) / gsz;
    int bm = pm * 256, bn = pn * 128;

    int tid  = threadIdx.x;
    int warp = tid >> 5, lane = tid & 31;
    int wm = warp & 3, wn = warp >> 2;       // 4m x 4n warp grid
    int gid = lane >> 2, tid4 = lane & 3;

    float acc[4][4][4];
    #pragma unroll
    for (int i = 0; i < 4; i++)
        #pragma unroll
        for (int j = 0; j < 4; j++)
            #pragma unroll
            for (int q = 0; q < 4; q++) acc[i][j][q] = 0.f;

    uint32_t smb = (uint32_t)__cvta_generic_to_shared(smf);
    const __half* Ag = A + (size_t)bm * K;
    const __half* Bg = B + (size_t)bn * K;

    uint32_t aoff[4], boff[2];
    #pragma unroll
    for (int mt = 0; mt < 4; mt++)
        aoff[mt] = (uint32_t)((wm * 64 + mt * 16 + (lane & 15)) * 80 + (lane >> 4) * 16);
    #pragma unroll
    for (int p = 0; p < 2; p++)
        boff[p] = (uint32_t)A5_B
                + (uint32_t)((wn * 32 + p * 16 + ((lane >> 4) * 8) + (lane & 7)) * 80
                             + (((lane >> 3) & 1) * 16));

    #define MM5_LOAD(KB, SS)                                                    \
    {                                                                           \
        int kt_ = (KB) * 32;                                                    \
        uint32_t sa_ = smb + (uint32_t)((SS) * ST5B);                           \
        uint32_t sb_ = sa_ + (uint32_t)A5_B;                                    \
        _Pragma("unroll")                                                       \
        for (int i_ = 0; i_ < 2; i_++) {                                        \
            int id_ = tid + i_ * 512;                                           \
            int r_ = id_ >> 2, c_ = id_ & 3;                                    \
            cp16(sa_ + (uint32_t)(r_ * 80 + c_ * 16),                           \
                 Ag + (size_t)r_ * K + kt_ + c_ * 8);                           \
        }                                                                       \
        {                                                                       \
            int r_ = tid >> 2, c_ = tid & 3;                                    \
            cp16(sb_ + (uint32_t)(r_ * 80 + c_ * 16),                           \
                 Bg + (size_t)r_ * K + kt_ + c_ * 8);                           \
        }                                                                       \
        asm volatile("cp.async.commit_group;\n");                               \
    }

    int ntiles = K >> 5;

    MM5_LOAD(0, 0)
    MM5_LOAD(1, 1)
    MM5_LOAD(2, 2)

    for (int t = 0; t < ntiles; t++) {
        if (t <= ntiles - 3) {
            asm volatile("cp.async.wait_group 2;\n");
        } else if (t == ntiles - 2) {
            asm volatile("cp.async.wait_group 1;\n");
        } else {
            asm volatile("cp.async.wait_group 0;\n");
        }
        __syncthreads();
        if (t + 3 < ntiles) MM5_LOAD(t + 3, (t + 3) & 3)

        uint32_t sbase = smb + (uint32_t)((t & 3) * ST5B);

        #pragma unroll
        for (int k16 = 0; k16 < 2; k16++) {
            uint32_t kb = (uint32_t)(k16 * 32);
            uint32_t af[4][4], bq0[4], bq1[4];
            #pragma unroll
            for (int mt = 0; mt < 4; mt++)
                ldsm4(af[mt], sbase + aoff[mt] + kb);
            ldsm4(bq0, sbase + boff[0] + kb);
            ldsm4(bq1, sbase + boff[1] + kb);

            #pragma unroll
            for (int mt = 0; mt < 4; mt++) {
                mma_f16(acc[mt][0], af[mt][0], af[mt][1], af[mt][2], af[mt][3], bq0[0], bq0[1]);
                mma_f16(acc[mt][1], af[mt][0], af[mt][1], af[mt][2], af[mt][3], bq0[2], bq0[3]);
                mma_f16(acc[mt][2], af[mt][0], af[mt][1], af[mt][2], af[mt][3], bq1[0], bq1[1]);
                mma_f16(acc[mt][3], af[mt][0], af[mt][1], af[mt][2], af[mt][3], bq1[2], bq1[3]);
            }
        }
    }

    __syncthreads();

    // epilogue
    #pragma unroll
    for (int mt = 0; mt < 4; mt++) {
        int r0 = bm + wm * 64 + mt * 16 + gid;
        #pragma unroll
        for (int nt = 0; nt < 4; nt++) {
            int c0 = bn + wn * 32 + nt * 8 + tid4 * 2;
            float2 v0 = make_float2(acc[mt][nt][0], acc[mt][nt][1]);
            float2 v1 = make_float2(acc[mt][nt][2], acc[mt][nt][3]);
            if (FINAL) {
                float gx = temb[2 * DIM + c0], gy = temb[2 * DIM + c0 + 1];
                float2 x0 = *(const float2*)(xres + (size_t)r0 * N + c0);
                float2 x1 = *(const float2*)(xres + (size_t)(r0 + 8) * N + c0);
                v0.x = x0.x + gx * v0.x; v0.y = x0.y + gy * v0.y;
                v1.x = x1.x + gx * v1.x; v1.y = x1.y + gy * v1.y;
            }
            if (sizeof(OutT) == 2) {
                *(__half2*)((__half*)C + (size_t)r0 * N + c0) =
                    __floats2half2_rn(v0.x, v0.y);
                *(__half2*)((__half*)C + (size_t)(r0 + 8) * N + c0) =
                    __floats2half2_rn(v1.x, v1.y);
            } else {
                *(float2*)((float*)C + (size_t)r0 * N + c0)       = v0;
                *(float2*)((float*)C + (size_t)(r0 + 8) * N + c0) = v1;
            }
        }
    }
}

// ---------------- kernel 3: QKV extract + RMSNorm + RoPE (-> half Q,K) ------
__global__ __launch_bounds__(128) void k_qkvprep(
    const __half* __restrict__ P, const float* __restrict__ cosb,
    const float* __restrict__ sinb, const float* __restrict__ nqw,
    const float* __restrict__ nkw,
    __half* __restrict__ Qb, __half* __restrict__ Kb)
{
    int s = blockIdx.x, h = blockIdx.y, d = threadIdx.x;
    const __half* row = P + (size_t)s * FOUT + h * HD;
    float q = __half2float(row[d]);
    float k = __half2float(row[DIM + d]);

    __shared__ float sQ[HD], sK[HD], sred[8];
    float sq = q * q, sk = k * k;
    #pragma unroll
    for (int o = 16; o; o >>= 1) {
        sq += __shfl_xor_sync(0xffffffffu, sq, o);
        sk += __shfl_xor_sync(0xffffffffu, sk, o);
    }
    int w = d >> 5;
    if ((d & 31) == 0) { sred[w] = sq; sred[4 + w] = sk; }
    __syncthreads();
    float ssq = sred[0] + sred[1] + sred[2] + sred[3];
    float ssk = sred[4] + sred[5] + sred[6] + sred[7];
    float qn = q * rsqrtf(ssq * (1.0f / HD) + EPS) * nqw[d];
    float kn = k * rsqrtf(ssk * (1.0f / HD) + EPS) * nkw[d];
    sQ[d] = qn; sK[d] = kn;
    __syncthreads();
    float qrot = (d & 1) ? sQ[d - 1] : -sQ[d + 1];
    float krot = (d & 1) ? sK[d - 1] : -sK[d + 1];
    float c  = cosb[(size_t)s * HD + d];
    float sn = sinb[(size_t)s * HD + d];
    const float scale = 0.08838834764831843f;
    size_t o = ((size_t)h * S_LEN + s) * HD + d;
    Qb[o] = __float2half_rn((qn * c + qrot * sn) * scale);
    Kb[o] = __float2half_rn(kn * c + krot * sn);
}

// ---------------- kernel 3b: V transpose (half [S][DIM] slice -> [DIM][S]) ---
__global__ __launch_bounds__(256) void k_vT(
    const __half* __restrict__ P, __half* __restrict__ Vt)
{
    __shared__ __half t[32][34];
    int c0 = blockIdx.x * 32, s0 = blockIdx.y * 32;
    int tx = threadIdx.x & 31, ty = threadIdx.x >> 5;
    #pragma unroll
    for (int i = 0; i < 32; i += 8)
        t[ty + i][tx] = P[(size_t)(s0 + ty + i) * FOUT + 2 * DIM + c0 + tx];
    __syncthreads();
    #pragma unroll
    for (int i = 0; i < 32; i += 8)
        Vt[(size_t)(c0 + ty + i) * S_LEN + s0 + tx] = t[tx][ty + i];
}

// ---------------- kernel 4: fp16 flash attention (ldmatrix, 3-stage) --------
#define K_STRH 136
#define V_STRH 72
#define P_STRH 72
#define K_STGH (64 * K_STRH)
#define V_STGH (128 * V_STRH)
#define PW_H   (16 * P_STRH)
#define ATT_STG 3
#define ATTN_SMEM ((ATT_STG * (K_STGH + V_STGH) + 8 * PW_H) * 2)   // 125952 B

__global__ __launch_bounds__(256, 1) void k_attn3(
    const __half* __restrict__ Qb, const __half* __restrict__ Kb,
    const __half* __restrict__ Vt, __half* __restrict__ attnout)
{
    extern __shared__ __half smh[];
    __half* Ps = smh + ATT_STG * (K_STGH + V_STGH);

    int h  = blockIdx.y;
    int q0 = blockIdx.x * 128;
    int tid = threadIdx.x, warp = tid >> 5, lane = tid & 31;
    int gid = lane >> 2, tid4 = lane & 3;
    __half* Pw = Ps + warp * PW_H;
    uint32_t smbase = (uint32_t)__cvta_generic_to_shared(smh);
    uint32_t pwbase = smbase + (uint32_t)(ATT_STG * (K_STGH + V_STGH) + warp * PW_H) * 2u;

    uint32_t kfoff = (uint32_t)((((lane >> 4) * 8) + (lane & 7)) * (K_STRH * 2)
                                + ((lane >> 3) & 1) * 16);
    uint32_t vfoff = (uint32_t)((((lane >> 4) * 8) + (lane & 7)) * (V_STRH * 2)
                                + ((lane >> 3) & 1) * 16);
    uint32_t pfoff = (uint32_t)((lane & 15) * (P_STRH * 2) + (lane >> 4) * 16);

    const __half* Qg = Qb + ((size_t)h * S_LEN + q0) * HD;
    #pragma unroll
    for (int i = 0; i < 8; i++) {
        int idx = tid + i * 256;
        int r = idx >> 4, c = idx & 15;
        cp16(smbase + (uint32_t)(r * K_STRH + c * 8) * 2u, Qg + (size_t)r * HD + c * 8);
    }
    asm volatile("cp.async.commit_group;\ncp.async.wait_group 0;\n");
    __syncthreads();
    uint32_t qf[8][4];
    {
        uint32_t qoff = smbase + (uint32_t)((warp * 16 + (lane & 15)) * (K_STRH * 2)
                                            + (lane >> 4) * 16);
        #pragma unroll
        for (int k16 = 0; k16 < 8; k16++)
            ldsm4(qf[k16], qoff + (uint32_t)(k16 * 32));
    }
    __syncthreads();

    float m0 = -1e30f, m1 = -1e30f, l0 = 0.f, l1 = 0.f;
    float o[16][4];
    #pragma unroll
    for (int dt = 0; dt < 16; dt++)
        #pragma unroll
        for (int j = 0; j < 4; j++) o[dt][j] = 0.f;

    #define LOAD_KV3(T, SS)                                                       \
    {                                                                             \
        const __half* Kg = Kb + ((size_t)h * S_LEN + (T) * 64) * HD;              \
        const __half* Vg = Vt + (size_t)h * HD * S_LEN + (T) * 64;                \
        uint32_t ks = smbase + (uint32_t)((SS) * (K_STGH + V_STGH)) * 2u;         \
        uint32_t vs = ks + (uint32_t)K_STGH * 2u;                                 \
        _Pragma("unroll")                                                         \
        for (int i = 0; i < 4; i++) {                                             \
            int idx = tid + i * 256;                                              \
            int kr = idx >> 4, kc = idx & 15;                                     \
            cp16(ks + (uint32_t)(kr * K_STRH + kc * 8) * 2u,                      \
                 Kg + (size_t)kr * HD + kc * 8);                                  \
            int vr = idx >> 3, vc = idx & 7;                                      \
            cp16(vs + (uint32_t)(vr * V_STRH + vc * 8) * 2u,                      \
                 Vg + (size_t)vr * S_LEN + vc * 8);                               \
        }                                                                         \
        asm volatile("cp.async.commit_group;\n");                                 \
    }

    LOAD_KV3(0, 0)
    LOAD_KV3(1, 1)

    int st = 0, sl = 2;
    for (int t = 0; t < 64; t++) {
        if (t < 62) {
            asm volatile("cp.async.wait_group 1;\n");
        } else {
            asm volatile("cp.async.wait_group 0;\n");
        }
        __syncthreads();
        if (t + 2 < 64) {
            LOAD_KV3(t + 2, sl)
            sl = (sl == 2) ? 0 : sl + 1;
        }

        uint32_t ksb = smbase + (uint32_t)(st * (K_STGH + V_STGH)) * 2u;
        uint32_t vsb = ksb + (uint32_t)K_STGH * 2u;
        st = (st == 2) ? 0 : st + 1;

        float sa[8][4];
        #pragma unroll
        for (int nt = 0; nt < 8; nt++)
            #pragma unroll
            for (int j = 0; j < 4; j++) sa[nt][j] = 0.f;
        #pragma unroll
        for (int ntp = 0; ntp < 4; ntp++) {
            uint32_t ka = ksb + kfoff + (uint32_t)(ntp * 16 * K_STRH * 2);
            #pragma unroll
            for (int k16 = 0; k16 < 8; k16++) {
                uint32_t bq[4];
                ldsm4(bq, ka + (uint32_t)(k16 * 32));
                mma_f16(sa[2 * ntp],     qf[k16][0], qf[k16][1], qf[k16][2], qf[k16][3],
                        bq[0], bq[1]);
                mma_f16(sa[2 * ntp + 1], qf[k16][0], qf[k16][1], qf[k16][2], qf[k16][3],
                        bq[2], bq[3]);
            }
        }

        float mx0 = -1e30f, mx1 = -1e30f;
        #pragma unroll
        for (int nt = 0; nt < 8; nt++) {
            mx0 = fmaxf(mx0, fmaxf(sa[nt][0], sa[nt][1]));
            mx1 = fmaxf(mx1, fmaxf(sa[nt][2], sa[nt][3]));
        }
        mx0 = fmaxf(mx0, __shfl_xor_sync(0xffffffffu, mx0, 1));
        mx0 = fmaxf(mx0, __shfl_xor_sync(0xffffffffu, mx0, 2));
        mx1 = fmaxf(mx1, __shfl_xor_sync(0xffffffffu, mx1, 1));
        mx1 = fmaxf(mx1, __shfl_xor_sync(0xffffffffu, mx1, 2));
        float nm0 = fmaxf(m0, mx0), nm1 = fmaxf(m1, mx1);
        float corr0 = __expf(m0 - nm0), corr1 = __expf(m1 - nm1);
        float rs0 = 0.f, rs1 = 0.f;
        #pragma unroll
        for (int nt = 0; nt < 8; nt++) {
            float p0 = __expf(sa[nt][0] - nm0);
            float p1 = __expf(sa[nt][1] - nm0);
            float p2 = __expf(sa[nt][2] - nm1);
            float p3 = __expf(sa[nt][3] - nm1);
            rs0 += p0 + p1; rs1 += p2 + p3;
            *(__half2*)&Pw[gid * P_STRH + nt * 8 + 2 * tid4]       = __floats2half2_rn(p0, p1);
            *(__half2*)&Pw[(gid + 8) * P_STRH + nt * 8 + 2 * tid4] = __floats2half2_rn(p2, p3);
        }
        rs0 += __shfl_xor_sync(0xffffffffu, rs0, 1);
        rs0 += __shfl_xor_sync(0xffffffffu, rs0, 2);
        rs1 += __shfl_xor_sync(0xffffffffu, rs1, 1);
        rs1 += __shfl_xor_sync(0xffffffffu, rs1, 2);
        l0 = l0 * corr0 + rs0;
        l1 = l1 * corr1 + rs1;
        m0 = nm0; m1 = nm1;
        #pragma unroll
        for (int dt = 0; dt < 16; dt++) {
            o[dt][0] *= corr0; o[dt][1] *= corr0;
            o[dt][2] *= corr1; o[dt][3] *= corr1;
        }
        __syncwarp();

        #pragma unroll
        for (int k16 = 0; k16 < 4; k16++) {
            uint32_t aq[4];
            ldsm4(aq, pwbase + pfoff + (uint32_t)(k16 * 32));
            #pragma unroll
            for (int dtp = 0; dtp < 8; dtp++) {
                uint32_t bq[4];
                ldsm4(bq, vsb + vfoff + (uint32_t)(dtp * 16 * V_STRH * 2 + k16 * 32));
                mma_f16(o[2 * dtp],     aq[0], aq[1], aq[2], aq[3], bq[0], bq[1]);
                mma_f16(o[2 * dtp + 1], aq[0], aq[1], aq[2], aq[3], bq[2], bq[3]);
            }
        }
        __syncwarp();
    }

    float inv0 = 1.0f / l0, inv1 = 1.0f / l1;
    int r0 = q0 + warp * 16 + gid;
    #pragma unroll
    for (int dt = 0; dt < 16; dt++) {
        int col = h * HD + dt * 8 + 2 * tid4;
        *(__half2*)&attnout[(size_t)r0 * CATK + col] =
            __floats2half2_rn(o[dt][0] * inv0, o[dt][1] * inv0);
        *(__half2*)&attnout[(size_t)(r0 + 8) * CATK + col] =
            __floats2half2_rn(o[dt][2] * inv1, o[dt][3] * inv1);
    }
}

// ---------------- kernel 5: SwiGLU -> half concat buffer ---------------------
__global__ __launch_bounds__(256) void k_swiglu(
    const __half* __restrict__ P, __half* __restrict__ cat)
{
    int j = blockIdx.x * 256 + threadIdx.x;
    int s = blockIdx.y;
    float a = __half2float(P[(size_t)s * FOUT + QKV + j]);
    float b = __half2float(P[(size_t)s * FOUT + QKV + MH + j]);
    cat[(size_t)s * CATK + DIM + j] = __float2half_rn((a / (1.f + __expf(-a))) * b);
}

// ---------------- launch -----------------------------------------------------
extern "C" void kernel_launch(void* const* d_in, const int* in_sizes, int n_in,
                              void* d_out, int out_size)
{
    const float* x       = (const float*)d_in[0];
    const float* temb    = (const float*)d_in[1];
    const float* rcos    = (const float*)d_in[2];
    const float* rsin    = (const float*)d_in[3];
    const float* w1      = (const float*)d_in[4];
    const float* wo_attn = (const float*)d_in[5];
    const float* wo_mlp  = (const float*)d_in[6];
    const float* nqw     = (const float*)d_in[7];
    const float* nkw     = (const float*)d_in[8];
    float* out = (float*)d_out;

    __half *h, *P, *Qb, *Kb, *Vt, *cat, *w1h, *woh;
    cudaGetSymbolAddress((void**)&h,   g_h);
    cudaGetSymbolAddress((void**)&P,   g_P);
    cudaGetSymbolAddress((void**)&Qb,  g_Qb);
    cudaGetSymbolAddress((void**)&Kb,  g_Kb);
    cudaGetSymbolAddress((void**)&Vt,  g_Vt);
    cudaGetSymbolAddress((void**)&cat, g_cat);
    cudaGetSymbolAddress((void**)&w1h, g_w1h);
    cudaGetSymbolAddress((void**)&woh, g_woh);

    // 0) weight convert + transpose to half [N][K]
    k_cvtT<<<dim3(FOUT / 32, DIM / 32), 256>>>(w1,      w1h, DIM, FOUT, DIM,  0);
    k_cvtT<<<dim3(DIM / 32,  DIM / 32), 256>>>(wo_attn, woh, DIM, DIM,  CATK, 0);
    k_cvtT<<<dim3(DIM / 32,  MH  / 32), 256>>>(wo_mlp,  woh, MH,  DIM,  CATK, DIM);

    // 1) LayerNorm + modulation -> half h
    k_lnmod<<<S_LEN, 256>>>(x, temb, h);

    cudaFuncSetAttribute((const void*)k_mm5<false, __half>,
                         cudaFuncAttributeMaxDynamicSharedMemorySize, MM_SMEM5);
    cudaFuncSetAttribute((const void*)k_mm5<true, float>,
                         cudaFuncAttributeMaxDynamicSharedMemorySize, MM_SMEM5);

    // 2) fused QKV+MLP projection: P = h @ w1 (half output)
    {
        int tm = S_LEN / 256, tn = FOUT / 128;
        k_mm5<false, __half><<<tm * tn, 512, MM_SMEM5>>>(
            h, w1h, P, S_LEN, FOUT, DIM, tm, tn, nullptr, nullptr);
    }

    // 3) Q/K heads + RMSNorm + RoPE (half); 3b) V transpose
    {
        dim3 g(S_LEN, HEADS);
        k_qkvprep<<<g, 128>>>(P, rcos, rsin, nqw, nkw, Qb, Kb);
        k_vT<<<dim3(DIM / 32, S_LEN / 32), 256>>>(P, Vt);
    }

    // 4) fp16 attention -> cat[:, 0:3072]
    {
        cudaFuncSetAttribute(k_attn3, cudaFuncAttributeMaxDynamicSharedMemorySize, ATTN_SMEM);
        dim3 g(S_LEN / 128, HEADS);
        k_attn3<<<g, 256, ATTN_SMEM>>>(Qb, Kb, Vt, cat);
    }

    // 5) SwiGLU -> cat[:, 3072:12288]
    {
        dim3 g(MH / 256, S_LEN);
        k_swiglu<<<g, 256>>>(P, cat);
    }

    // 6) out = x + gate * (cat @ [wo_attn ; wo_mlp])   (K = 12288)
    {
        int tm = S_LEN / 256, tn = DIM / 128;
        k_mm5<true, float><<<tm * tn, 512, MM_SMEM5>>>(
            cat, woh, out, S_LEN, DIM, CATK, tm, tn, x, temb);
    }
}

// round 14
// speedup vs baseline: 1.1453x; 1.1453x over previous
#include <cuda_runtime.h>
#include <cuda_fp16.h>
#include <math.h>
#include <stdint.h>

#define S_LEN 4096
#define DIM   3072
#define HEADS 24
#define HD    128
#define MH    9216
#define FOUT  27648      // 3*DIM + 2*MH
#define QKV   9216       // 3*DIM
#define CATK  12288      // DIM + MH
#define EPS   1e-6f

// ---------------- scratch (device globals; no allocations allowed) ----------
__device__ __half g_h   [(size_t)S_LEN * DIM];
__device__ __half g_P   [(size_t)S_LEN * FOUT];
__device__ __half g_Qb  [(size_t)HEADS * S_LEN * HD];   // [h][s][d], pre-scaled
__device__ __half g_Kb  [(size_t)HEADS * S_LEN * HD];   // [h][s][d]
__device__ __half g_Vt  [(size_t)DIM * S_LEN];          // [h*HD+d][s]
__device__ __half g_cat [(size_t)S_LEN * CATK];         // [attn | swiglu]
__device__ __half g_w1h [(size_t)FOUT * DIM];           // w1^T [FOUT][DIM]
__device__ __half g_woh [(size_t)DIM * CATK];           // [wo_attn;wo_mlp]^T

__device__ __forceinline__ void cp16(uint32_t s, const void* g) {
    asm volatile("cp.async.cg.shared.global [%0], [%1], 16;\n" :: "r"(s), "l"(g));
}
__device__ __forceinline__ void mma_f16(float c[4],
    uint32_t a0, uint32_t a1, uint32_t a2, uint32_t a3, uint32_t b0, uint32_t b1)
{
    asm volatile(
        "mma.sync.aligned.m16n8k16.row.col.f32.f16.f16.f32 "
        "{%0,%1,%2,%3},{%4,%5,%6,%7},{%8,%9},{%0,%1,%2,%3};"
        : "+f"(c[0]), "+f"(c[1]), "+f"(c[2]), "+f"(c[3])
        : "r"(a0), "r"(a1), "r"(a2), "r"(a3), "r"(b0), "r"(b1));
}
__device__ __forceinline__ void ldsm4(uint32_t r[4], uint32_t addr) {
    asm volatile("ldmatrix.sync.aligned.m8n8.x4.shared.b16 {%0,%1,%2,%3}, [%4];"
                 : "=r"(r[0]), "=r"(r[1]), "=r"(r[2]), "=r"(r[3]) : "r"(addr));
}

// ---------------- kernel 0: fp32 [K][N] -> half [N][outK] transpose ----------
__global__ __launch_bounds__(256) void k_cvtT(
    const float* __restrict__ in, __half* __restrict__ out,
    int K, int N, int outK, int kofs)
{
    __shared__ float t[32][33];
    int k0 = blockIdx.y * 32, n0 = blockIdx.x * 32;
    int tx = threadIdx.x & 31, ty = threadIdx.x >> 5;
    #pragma unroll
    for (int i = 0; i < 32; i += 8)
        t[ty + i][tx] = in[(size_t)(k0 + ty + i) * N + n0 + tx];
    __syncthreads();
    #pragma unroll
    for (int i = 0; i < 32; i += 8)
        out[(size_t)(n0 + ty + i) * outK + kofs + k0 + tx] = __float2half_rn(t[tx][ty + i]);
}

// ---------------- kernel 1: LayerNorm + modulation (-> half) -----------------
__global__ __launch_bounds__(256) void k_lnmod(
    const float* __restrict__ x, const float* __restrict__ temb,
    __half* __restrict__ h)
{
    int s = blockIdx.x;
    const float* xr = x + (size_t)s * DIM;
    float v[12];
    float lsum = 0.f, lsq = 0.f;
    #pragma unroll
    for (int i = 0; i < 12; i++) {
        float t = xr[threadIdx.x + i * 256];
        v[i] = t; lsum += t; lsq += t * t;
    }
    __shared__ float red[16];
    #pragma unroll
    for (int o = 16; o; o >>= 1) {
        lsum += __shfl_xor_sync(0xffffffffu, lsum, o);
        lsq  += __shfl_xor_sync(0xffffffffu, lsq,  o);
    }
    int w = threadIdx.x >> 5;
    if ((threadIdx.x & 31) == 0) { red[w] = lsum; red[8 + w] = lsq; }
    __syncthreads();
    float ssum = 0.f, ssq = 0.f;
    #pragma unroll
    for (int i = 0; i < 8; i++) { ssum += red[i]; ssq += red[8 + i]; }
    float mu  = ssum * (1.0f / DIM);
    float var = ssq * (1.0f / DIM) - mu * mu;
    float rs  = rsqrtf(var + EPS);
    __half* hr = h + (size_t)s * DIM;
    #pragma unroll
    for (int i = 0; i < 12; i++) {
        int d = threadIdx.x + i * 256;
        float sc = temb[DIM + d];
        float sh = temb[d];
        hr[d] = __float2half_rn((v[i] - mu) * rs * (1.f + sc) + sh);
    }
}

// ---------------- kernel 2: fp16 GEMM, 128x128 CTA, BK=64, 2 CTAs/SM --------
// Row stride 144 B (36 words ≡ 4 mod 32: conflict-free ldmatrix phases).
#define MM6_STG 3
#define A6_B  18432                      // 128 rows * 144 B
#define ST6B  (2 * A6_B)                 // A + B = 36864 B per stage
#define MM_SMEM6 (MM6_STG * ST6B)        // 110592 B

template <bool FINAL, typename OutT>
__global__ __launch_bounds__(256, 2) void k_mm6(
    const __half* __restrict__ A, const __half* __restrict__ B,
    OutT* __restrict__ C, int M, int N, int K, int tiles_m, int tiles_n,
    const float* __restrict__ xres, const float* __restrict__ temb)
{
    extern __shared__ float smf[];

    int pid = blockIdx.x;
    const int GROUPM = 16;
    int npg     = GROUPM * tiles_n;
    int groupid = pid / npg;
    int firstm  = groupid * GROUPM;
    int gsz     = min(GROUPM, tiles_m - firstm);
    int pm      = firstm + (pid % npg) % gsz;
    int pn      = (pid % npg) / gsz;
    int bm = pm * 128, bn = pn * 128;

    int tid  = threadIdx.x;
    int warp = tid >> 5, lane = tid & 31;
    int wm = warp & 1, wn = warp >> 1;       // 2m x 4n warp grid
    int gid = lane >> 2, tid4 = lane & 3;

    float acc[4][4][4];
    #pragma unroll
    for (int i = 0; i < 4; i++)
        #pragma unroll
        for (int j = 0; j < 4; j++)
            #pragma unroll
            for (int q = 0; q < 4; q++) acc[i][j][q] = 0.f;

    uint32_t smb = (uint32_t)__cvta_generic_to_shared(smf);
    const __half* Ag = A + (size_t)bm * K;
    const __half* Bg = B + (size_t)bn * K;

    uint32_t aoff[4], boff[2];
    #pragma unroll
    for (int mt = 0; mt < 4; mt++)
        aoff[mt] = (uint32_t)((wm * 64 + mt * 16 + (lane & 15)) * 144 + (lane >> 4) * 16);
    #pragma unroll
    for (int p = 0; p < 2; p++)
        boff[p] = (uint32_t)A6_B
                + (uint32_t)((wn * 32 + p * 16 + ((lane >> 4) * 8) + (lane & 7)) * 144
                             + (((lane >> 3) & 1) * 16));

    // Loader: per stage A = 1024 16B-chunks (128 rows x 8), B same.
    #define MM6_LOAD(KB, SS)                                                    \
    {                                                                           \
        int kt_ = (KB) * 64;                                                    \
        uint32_t sa_ = smb + (uint32_t)((SS) * ST6B);                           \
        uint32_t sb_ = sa_ + (uint32_t)A6_B;                                    \
        _Pragma("unroll")                                                       \
        for (int i_ = 0; i_ < 4; i_++) {                                        \
            int id_ = tid + i_ * 256;                                           \
            int r_ = id_ >> 3, c_ = id_ & 7;                                    \
            cp16(sa_ + (uint32_t)(r_ * 144 + c_ * 16),                          \
                 Ag + (size_t)r_ * K + kt_ + c_ * 8);                           \
            cp16(sb_ + (uint32_t)(r_ * 144 + c_ * 16),                          \
                 Bg + (size_t)r_ * K + kt_ + c_ * 8);                           \
        }                                                                       \
        asm volatile("cp.async.commit_group;\n");                               \
    }

    int ntiles = K >> 6;

    MM6_LOAD(0, 0)
    MM6_LOAD(1, 1)

    int st = 0, sl = 2;
    for (int t = 0; t < ntiles; t++) {
        if (t < ntiles - 2) {
            asm volatile("cp.async.wait_group 1;\n");
        } else {
            asm volatile("cp.async.wait_group 0;\n");
        }
        __syncthreads();
        if (t + 2 < ntiles) {
            MM6_LOAD(t + 2, sl)
            sl = (sl == 2) ? 0 : sl + 1;
        }

        uint32_t sbase = smb + (uint32_t)(st * ST6B);
        st = (st == 2) ? 0 : st + 1;

        #pragma unroll
        for (int k16 = 0; k16 < 4; k16++) {
            uint32_t kb = (uint32_t)(k16 * 32);
            uint32_t af[4][4], bq0[4], bq1[4];
            #pragma unroll
            for (int mt = 0; mt < 4; mt++)
                ldsm4(af[mt], sbase + aoff[mt] + kb);
            ldsm4(bq0, sbase + boff[0] + kb);
            ldsm4(bq1, sbase + boff[1] + kb);

            #pragma unroll
            for (int mt = 0; mt < 4; mt++) {
                mma_f16(acc[mt][0], af[mt][0], af[mt][1], af[mt][2], af[mt][3], bq0[0], bq0[1]);
                mma_f16(acc[mt][1], af[mt][0], af[mt][1], af[mt][2], af[mt][3], bq0[2], bq0[3]);
                mma_f16(acc[mt][2], af[mt][0], af[mt][1], af[mt][2], af[mt][3], bq1[0], bq1[1]);
                mma_f16(acc[mt][3], af[mt][0], af[mt][1], af[mt][2], af[mt][3], bq1[2], bq1[3]);
            }
        }
    }

    __syncthreads();

    // epilogue
    #pragma unroll
    for (int mt = 0; mt < 4; mt++) {
        int r0 = bm + wm * 64 + mt * 16 + gid;
        #pragma unroll
        for (int nt = 0; nt < 4; nt++) {
            int c0 = bn + wn * 32 + nt * 8 + tid4 * 2;
            float2 v0 = make_float2(acc[mt][nt][0], acc[mt][nt][1]);
            float2 v1 = make_float2(acc[mt][nt][2], acc[mt][nt][3]);
            if (FINAL) {
                float gx = temb[2 * DIM + c0], gy = temb[2 * DIM + c0 + 1];
                float2 x0 = *(const float2*)(xres + (size_t)r0 * N + c0);
                float2 x1 = *(const float2*)(xres + (size_t)(r0 + 8) * N + c0);
                v0.x = x0.x + gx * v0.x; v0.y = x0.y + gy * v0.y;
                v1.x = x1.x + gx * v1.x; v1.y = x1.y + gy * v1.y;
            }
            if (sizeof(OutT) == 2) {
                *(__half2*)((__half*)C + (size_t)r0 * N + c0) =
                    __floats2half2_rn(v0.x, v0.y);
                *(__half2*)((__half*)C + (size_t)(r0 + 8) * N + c0) =
                    __floats2half2_rn(v1.x, v1.y);
            } else {
                *(float2*)((float*)C + (size_t)r0 * N + c0)       = v0;
                *(float2*)((float*)C + (size_t)(r0 + 8) * N + c0) = v1;
            }
        }
    }
}

// ---------------- kernel 3: QKV extract + RMSNorm + RoPE (-> half Q,K) ------
__global__ __launch_bounds__(128) void k_qkvprep(
    const __half* __restrict__ P, const float* __restrict__ cosb,
    const float* __restrict__ sinb, const float* __restrict__ nqw,
    const float* __restrict__ nkw,
    __half* __restrict__ Qb, __half* __restrict__ Kb)
{
    int s = blockIdx.x, h = blockIdx.y, d = threadIdx.x;
    const __half* row = P + (size_t)s * FOUT + h * HD;
    float q = __half2float(row[d]);
    float k = __half2float(row[DIM + d]);

    __shared__ float sQ[HD], sK[HD], sred[8];
    float sq = q * q, sk = k * k;
    #pragma unroll
    for (int o = 16; o; o >>= 1) {
        sq += __shfl_xor_sync(0xffffffffu, sq, o);
        sk += __shfl_xor_sync(0xffffffffu, sk, o);
    }
    int w = d >> 5;
    if ((d & 31) == 0) { sred[w] = sq; sred[4 + w] = sk; }
    __syncthreads();
    float ssq = sred[0] + sred[1] + sred[2] + sred[3];
    float ssk = sred[4] + sred[5] + sred[6] + sred[7];
    float qn = q * rsqrtf(ssq * (1.0f / HD) + EPS) * nqw[d];
    float kn = k * rsqrtf(ssk * (1.0f / HD) + EPS) * nkw[d];
    sQ[d] = qn; sK[d] = kn;
    __syncthreads();
    float qrot = (d & 1) ? sQ[d - 1] : -sQ[d + 1];
    float krot = (d & 1) ? sK[d - 1] : -sK[d + 1];
    float c  = cosb[(size_t)s * HD + d];
    float sn = sinb[(size_t)s * HD + d];
    const float scale = 0.08838834764831843f;
    size_t o = ((size_t)h * S_LEN + s) * HD + d;
    Qb[o] = __float2half_rn((qn * c + qrot * sn) * scale);
    Kb[o] = __float2half_rn(kn * c + krot * sn);
}

// ---------------- kernel 3b: V transpose (half [S][DIM] slice -> [DIM][S]) ---
__global__ __launch_bounds__(256) void k_vT(
    const __half* __restrict__ P, __half* __restrict__ Vt)
{
    __shared__ __half t[32][34];
    int c0 = blockIdx.x * 32, s0 = blockIdx.y * 32;
    int tx = threadIdx.x & 31, ty = threadIdx.x >> 5;
    #pragma unroll
    for (int i = 0; i < 32; i += 8)
        t[ty + i][tx] = P[(size_t)(s0 + ty + i) * FOUT + 2 * DIM + c0 + tx];
    __syncthreads();
    #pragma unroll
    for (int i = 0; i < 32; i += 8)
        Vt[(size_t)(c0 + ty + i) * S_LEN + s0 + tx] = t[tx][ty + i];
}

// ---------------- kernel 4: fp16 flash attention (ldmatrix, 3-stage) --------
#define K_STRH 136
#define V_STRH 72
#define P_STRH 72
#define K_STGH (64 * K_STRH)
#define V_STGH (128 * V_STRH)
#define PW_H   (16 * P_STRH)
#define ATT_STG 3
#define ATTN_SMEM ((ATT_STG * (K_STGH + V_STGH) + 8 * PW_H) * 2)   // 125952 B

__global__ __launch_bounds__(256, 1) void k_attn3(
    const __half* __restrict__ Qb, const __half* __restrict__ Kb,
    const __half* __restrict__ Vt, __half* __restrict__ attnout)
{
    extern __shared__ __half smh[];
    __half* Ps = smh + ATT_STG * (K_STGH + V_STGH);

    int h  = blockIdx.y;
    int q0 = blockIdx.x * 128;
    int tid = threadIdx.x, warp = tid >> 5, lane = tid & 31;
    int gid = lane >> 2, tid4 = lane & 3;
    __half* Pw = Ps + warp * PW_H;
    uint32_t smbase = (uint32_t)__cvta_generic_to_shared(smh);
    uint32_t pwbase = smbase + (uint32_t)(ATT_STG * (K_STGH + V_STGH) + warp * PW_H) * 2u;

    uint32_t kfoff = (uint32_t)((((lane >> 4) * 8) + (lane & 7)) * (K_STRH * 2)
                                + ((lane >> 3) & 1) * 16);
    uint32_t vfoff = (uint32_t)((((lane >> 4) * 8) + (lane & 7)) * (V_STRH * 2)
                                + ((lane >> 3) & 1) * 16);
    uint32_t pfoff = (uint32_t)((lane & 15) * (P_STRH * 2) + (lane >> 4) * 16);

    const __half* Qg = Qb + ((size_t)h * S_LEN + q0) * HD;
    #pragma unroll
    for (int i = 0; i < 8; i++) {
        int idx = tid + i * 256;
        int r = idx >> 4, c = idx & 15;
        cp16(smbase + (uint32_t)(r * K_STRH + c * 8) * 2u, Qg + (size_t)r * HD + c * 8);
    }
    asm volatile("cp.async.commit_group;\ncp.async.wait_group 0;\n");
    __syncthreads();
    uint32_t qf[8][4];
    {
        uint32_t qoff = smbase + (uint32_t)((warp * 16 + (lane & 15)) * (K_STRH * 2)
                                            + (lane >> 4) * 16);
        #pragma unroll
        for (int k16 = 0; k16 < 8; k16++)
            ldsm4(qf[k16], qoff + (uint32_t)(k16 * 32));
    }
    __syncthreads();

    float m0 = -1e30f, m1 = -1e30f, l0 = 0.f, l1 = 0.f;
    float o[16][4];
    #pragma unroll
    for (int dt = 0; dt < 16; dt++)
        #pragma unroll
        for (int j = 0; j < 4; j++) o[dt][j] = 0.f;

    #define LOAD_KV3(T, SS)                                                       \
    {                                                                             \
        const __half* Kg = Kb + ((size_t)h * S_LEN + (T) * 64) * HD;              \
        const __half* Vg = Vt + (size_t)h * HD * S_LEN + (T) * 64;                \
        uint32_t ks = smbase + (uint32_t)((SS) * (K_STGH + V_STGH)) * 2u;         \
        uint32_t vs = ks + (uint32_t)K_STGH * 2u;                                 \
        _Pragma("unroll")                                                         \
        for (int i = 0; i < 4; i++) {                                             \
            int idx = tid + i * 256;                                              \
            int kr = idx >> 4, kc = idx & 15;                                     \
            cp16(ks + (uint32_t)(kr * K_STRH + kc * 8) * 2u,                      \
                 Kg + (size_t)kr * HD + kc * 8);                                  \
            int vr = idx >> 3, vc = idx & 7;                                      \
            cp16(vs + (uint32_t)(vr * V_STRH + vc * 8) * 2u,                      \
                 Vg + (size_t)vr * S_LEN + vc * 8);                               \
        }                                                                         \
        asm volatile("cp.async.commit_group;\n");                                 \
    }

    LOAD_KV3(0, 0)
    LOAD_KV3(1, 1)

    int st = 0, sl = 2;
    for (int t = 0; t < 64; t++) {
        if (t < 62) {
            asm volatile("cp.async.wait_group 1;\n");
        } else {
            asm volatile("cp.async.wait_group 0;\n");
        }
        __syncthreads();
        if (t + 2 < 64) {
            LOAD_KV3(t + 2, sl)
            sl = (sl == 2) ? 0 : sl + 1;
        }

        uint32_t ksb = smbase + (uint32_t)(st * (K_STGH + V_STGH)) * 2u;
        uint32_t vsb = ksb + (uint32_t)K_STGH * 2u;
        st = (st == 2) ? 0 : st + 1;

        float sa[8][4];
        #pragma unroll
        for (int nt = 0; nt < 8; nt++)
            #pragma unroll
            for (int j = 0; j < 4; j++) sa[nt][j] = 0.f;
        #pragma unroll
        for (int ntp = 0; ntp < 4; ntp++) {
            uint32_t ka = ksb + kfoff + (uint32_t)(ntp * 16 * K_STRH * 2);
            #pragma unroll
            for (int k16 = 0; k16 < 8; k16++) {
                uint32_t bq[4];
                ldsm4(bq, ka + (uint32_t)(k16 * 32));
                mma_f16(sa[2 * ntp],     qf[k16][0], qf[k16][1], qf[k16][2], qf[k16][3],
                        bq[0], bq[1]);
                mma_f16(sa[2 * ntp + 1], qf[k16][0], qf[k16][1], qf[k16][2], qf[k16][3],
                        bq[2], bq[3]);
            }
        }

        float mx0 = -1e30f, mx1 = -1e30f;
        #pragma unroll
        for (int nt = 0; nt < 8; nt++) {
            mx0 = fmaxf(mx0, fmaxf(sa[nt][0], sa[nt][1]));
            mx1 = fmaxf(mx1, fmaxf(sa[nt][2], sa[nt][3]));
        }
        mx0 = fmaxf(mx0, __shfl_xor_sync(0xffffffffu, mx0, 1));
        mx0 = fmaxf(mx0, __shfl_xor_sync(0xffffffffu, mx0, 2));
        mx1 = fmaxf(mx1, __shfl_xor_sync(0xffffffffu, mx1, 1));
        mx1 = fmaxf(mx1, __shfl_xor_sync(0xffffffffu, mx1, 2));
        float nm0 = fmaxf(m0, mx0), nm1 = fmaxf(m1, mx1);
        float corr0 = __expf(m0 - nm0), corr1 = __expf(m1 - nm1);
        float rs0 = 0.f, rs1 = 0.f;
        #pragma unroll
        for (int nt = 0; nt < 8; nt++) {
            float p0 = __expf(sa[nt][0] - nm0);
            float p1 = __expf(sa[nt][1] - nm0);
            float p2 = __expf(sa[nt][2] - nm1);
            float p3 = __expf(sa[nt][3] - nm1);
            rs0 += p0 + p1; rs1 += p2 + p3;
            *(__half2*)&Pw[gid * P_STRH + nt * 8 + 2 * tid4]       = __floats2half2_rn(p0, p1);
            *(__half2*)&Pw[(gid + 8) * P_STRH + nt * 8 + 2 * tid4] = __floats2half2_rn(p2, p3);
        }
        rs0 += __shfl_xor_sync(0xffffffffu, rs0, 1);
        rs0 += __shfl_xor_sync(0xffffffffu, rs0, 2);
        rs1 += __shfl_xor_sync(0xffffffffu, rs1, 1);
        rs1 += __shfl_xor_sync(0xffffffffu, rs1, 2);
        l0 = l0 * corr0 + rs0;
        l1 = l1 * corr1 + rs1;
        m0 = nm0; m1 = nm1;
        #pragma unroll
        for (int dt = 0; dt < 16; dt++) {
            o[dt][0] *= corr0; o[dt][1] *= corr0;
            o[dt][2] *= corr1; o[dt][3] *= corr1;
        }
        __syncwarp();

        #pragma unroll
        for (int k16 = 0; k16 < 4; k16++) {
            uint32_t aq[4];
            ldsm4(aq, pwbase + pfoff + (uint32_t)(k16 * 32));
            #pragma unroll
            for (int dtp = 0; dtp < 8; dtp++) {
                uint32_t bq[4];
                ldsm4(bq, vsb + vfoff + (uint32_t)(dtp * 16 * V_STRH * 2 + k16 * 32));
                mma_f16(o[2 * dtp],     aq[0], aq[1], aq[2], aq[3], bq[0], bq[1]);
                mma_f16(o[2 * dtp + 1], aq[0], aq[1], aq[2], aq[3], bq[2], bq[3]);
            }
        }
        __syncwarp();
    }

    float inv0 = 1.0f / l0, inv1 = 1.0f / l1;
    int r0 = q0 + warp * 16 + gid;
    #pragma unroll
    for (int dt = 0; dt < 16; dt++) {
        int col = h * HD + dt * 8 + 2 * tid4;
        *(__half2*)&attnout[(size_t)r0 * CATK + col] =
            __floats2half2_rn(o[dt][0] * inv0, o[dt][1] * inv0);
        *(__half2*)&attnout[(size_t)(r0 + 8) * CATK + col] =
            __floats2half2_rn(o[dt][2] * inv1, o[dt][3] * inv1);
    }
}

// ---------------- kernel 5: SwiGLU -> half concat buffer ---------------------
__global__ __launch_bounds__(256) void k_swiglu(
    const __half* __restrict__ P, __half* __restrict__ cat)
{
    int j = blockIdx.x * 256 + threadIdx.x;
    int s = blockIdx.y;
    float a = __half2float(P[(size_t)s * FOUT + QKV + j]);
    float b = __half2float(P[(size_t)s * FOUT + QKV + MH + j]);
    cat[(size_t)s * CATK + DIM + j] = __float2half_rn((a / (1.f + __expf(-a))) * b);
}

// ---------------- launch -----------------------------------------------------
extern "C" void kernel_launch(void* const* d_in, const int* in_sizes, int n_in,
                              void* d_out, int out_size)
{
    const float* x       = (const float*)d_in[0];
    const float* temb    = (const float*)d_in[1];
    const float* rcos    = (const float*)d_in[2];
    const float* rsin    = (const float*)d_in[3];
    const float* w1      = (const float*)d_in[4];
    const float* wo_attn = (const float*)d_in[5];
    const float* wo_mlp  = (const float*)d_in[6];
    const float* nqw     = (const float*)d_in[7];
    const float* nkw     = (const float*)d_in[8];
    float* out = (float*)d_out;

    __half *h, *P, *Qb, *Kb, *Vt, *cat, *w1h, *woh;
    cudaGetSymbolAddress((void**)&h,   g_h);
    cudaGetSymbolAddress((void**)&P,   g_P);
    cudaGetSymbolAddress((void**)&Qb,  g_Qb);
    cudaGetSymbolAddress((void**)&Kb,  g_Kb);
    cudaGetSymbolAddress((void**)&Vt,  g_Vt);
    cudaGetSymbolAddress((void**)&cat, g_cat);
    cudaGetSymbolAddress((void**)&w1h, g_w1h);
    cudaGetSymbolAddress((void**)&woh, g_woh);

    // 0) weight convert + transpose to half [N][K]
    k_cvtT<<<dim3(FOUT / 32, DIM / 32), 256>>>(w1,      w1h, DIM, FOUT, DIM,  0);
    k_cvtT<<<dim3(DIM / 32,  DIM / 32), 256>>>(wo_attn, woh, DIM, DIM,  CATK, 0);
    k_cvtT<<<dim3(DIM / 32,  MH  / 32), 256>>>(wo_mlp,  woh, MH,  DIM,  CATK, DIM);

    // 1) LayerNorm + modulation -> half h
    k_lnmod<<<S_LEN, 256>>>(x, temb, h);

    cudaFuncSetAttribute((const void*)k_mm6<false, __half>,
                         cudaFuncAttributeMaxDynamicSharedMemorySize, MM_SMEM6);
    cudaFuncSetAttribute((const void*)k_mm6<true, float>,
                         cudaFuncAttributeMaxDynamicSharedMemorySize, MM_SMEM6);

    // 2) fused QKV+MLP projection: P = h @ w1 (half output)
    {
        int tm = S_LEN / 128, tn = FOUT / 128;
        k_mm6<false, __half><<<tm * tn, 256, MM_SMEM6>>>(
            h, w1h, P, S_LEN, FOUT, DIM, tm, tn, nullptr, nullptr);
    }

    // 3) Q/K heads + RMSNorm + RoPE (half); 3b) V transpose
    {
        dim3 g(S_LEN, HEADS);
        k_qkvprep<<<g, 128>>>(P, rcos, rsin, nqw, nkw, Qb, Kb);
        k_vT<<<dim3(DIM / 32, S_LEN / 32), 256>>>(P, Vt);
    }

    // 4) fp16 attention -> cat[:, 0:3072]
    {
        cudaFuncSetAttribute(k_attn3, cudaFuncAttributeMaxDynamicSharedMemorySize, ATTN_SMEM);
        dim3 g(S_LEN / 128, HEADS);
        k_attn3<<<g, 256, ATTN_SMEM>>>(Qb, Kb, Vt, cat);
    }

    // 5) SwiGLU -> cat[:, 3072:12288]
    {
        dim3 g(MH / 256, S_LEN);
        k_swiglu<<<g, 256>>>(P, cat);
    }

    // 6) out = x + gate * (cat @ [wo_attn ; wo_mlp])   (K = 12288)
    {
        int tm = S_LEN / 128, tn = DIM / 128;
        k_mm6<true, float><<<tm * tn, 256, MM_SMEM6>>>(
            cat, woh, out, S_LEN, DIM, CATK, tm, tn, x, temb);
    }
}

// round 15
// speedup vs baseline: 1.1735x; 1.0247x over previous
#include <cuda_runtime.h>
#include <cuda_fp16.h>
#include <math.h>
#include <stdint.h>

#define S_LEN 4096
#define DIM   3072
#define HEADS 24
#define HD    128
#define MH    9216
#define FOUT  27648      // 3*DIM + 2*MH
#define QKV   9216       // 3*DIM
#define CATK  12288      // DIM + MH
#define EPS   1e-6f

// ---------------- scratch (device globals; no allocations allowed) ----------
__device__ __half g_h   [(size_t)S_LEN * DIM];
__device__ __half g_P   [(size_t)S_LEN * FOUT];
__device__ __half g_Qb  [(size_t)HEADS * S_LEN * HD];   // [h][s][d], pre-scaled
__device__ __half g_Kb  [(size_t)HEADS * S_LEN * HD];   // [h][s][d]
__device__ __half g_Vt  [(size_t)DIM * S_LEN];          // [h*HD+d][s]
__device__ __half g_cat [(size_t)S_LEN * CATK];         // [attn | swiglu]
__device__ __half g_w1h [(size_t)FOUT * DIM];           // w1^T, MLP cols interleaved
__device__ __half g_woh [(size_t)DIM * CATK];           // [wo_attn;wo_mlp]^T

__device__ __forceinline__ void cp16(uint32_t s, const void* g) {
    asm volatile("cp.async.cg.shared.global [%0], [%1], 16;\n" :: "r"(s), "l"(g));
}
__device__ __forceinline__ void mma_f16(float c[4],
    uint32_t a0, uint32_t a1, uint32_t a2, uint32_t a3, uint32_t b0, uint32_t b1)
{
    asm volatile(
        "mma.sync.aligned.m16n8k16.row.col.f32.f16.f16.f32 "
        "{%0,%1,%2,%3},{%4,%5,%6,%7},{%8,%9},{%0,%1,%2,%3};"
        : "+f"(c[0]), "+f"(c[1]), "+f"(c[2]), "+f"(c[3])
        : "r"(a0), "r"(a1), "r"(a2), "r"(a3), "r"(b0), "r"(b1));
}
__device__ __forceinline__ void ldsm4(uint32_t r[4], uint32_t addr) {
    asm volatile("ldmatrix.sync.aligned.m8n8.x4.shared.b16 {%0,%1,%2,%3}, [%4];"
                 : "=r"(r[0]), "=r"(r[1]), "=r"(r[2]), "=r"(r[3]) : "r"(addr));
}

// ---------------- kernel 0: fp32 [K][cols] -> half [row][outK] transpose -----
// out row for source column n is rowBase + n*rowStride (enables interleave).
__global__ __launch_bounds__(256) void k_cvtT(
    const float* __restrict__ in, __half* __restrict__ out,
    int srcStride, int outK, int kofs, int rowBase, int rowStride)
{
    __shared__ float t[32][33];
    int k0 = blockIdx.y * 32, n0 = blockIdx.x * 32;
    int tx = threadIdx.x & 31, ty = threadIdx.x >> 5;
    #pragma unroll
    for (int i = 0; i < 32; i += 8)
        t[ty + i][tx] = in[(size_t)(k0 + ty + i) * srcStride + n0 + tx];
    __syncthreads();
    #pragma unroll
    for (int i = 0; i < 32; i += 8)
        out[((size_t)rowBase + (size_t)(n0 + ty + i) * rowStride) * outK + kofs + k0 + tx]
            = __float2half_rn(t[tx][ty + i]);
}

// ---------------- kernel 1: LayerNorm + modulation (-> half) -----------------
__global__ __launch_bounds__(256) void k_lnmod(
    const float* __restrict__ x, const float* __restrict__ temb,
    __half* __restrict__ h)
{
    int s = blockIdx.x;
    const float* xr = x + (size_t)s * DIM;
    float v[12];
    float lsum = 0.f, lsq = 0.f;
    #pragma unroll
    for (int i = 0; i < 12; i++) {
        float t = xr[threadIdx.x + i * 256];
        v[i] = t; lsum += t; lsq += t * t;
    }
    __shared__ float red[16];
    #pragma unroll
    for (int o = 16; o; o >>= 1) {
        lsum += __shfl_xor_sync(0xffffffffu, lsum, o);
        lsq  += __shfl_xor_sync(0xffffffffu, lsq,  o);
    }
    int w = threadIdx.x >> 5;
    if ((threadIdx.x & 31) == 0) { red[w] = lsum; red[8 + w] = lsq; }
    __syncthreads();
    float ssum = 0.f, ssq = 0.f;
    #pragma unroll
    for (int i = 0; i < 8; i++) { ssum += red[i]; ssq += red[8 + i]; }
    float mu  = ssum * (1.0f / DIM);
    float var = ssq * (1.0f / DIM) - mu * mu;
    float rs  = rsqrtf(var + EPS);
    __half* hr = h + (size_t)s * DIM;
    #pragma unroll
    for (int i = 0; i < 12; i++) {
        int d = threadIdx.x + i * 256;
        float sc = temb[DIM + d];
        float sh = temb[d];
        hr[d] = __float2half_rn((v[i] - mu) * rs * (1.f + sc) + sh);
    }
}

// ---------------- kernel 2: fp16 GEMM, 128x128 CTA, BK=64, 2 CTAs/SM --------
// MODE 1: GEMM1 — QKV tiles write half to P; MLP tiles (interleaved gate/up)
//         compute silu(a)*b in fp32 and write half to cat[:, DIM + j].
// MODE 2: FINAL — out = x + gate * acc (fp32 out).
#define MM6_STG 3
#define A6_B  18432                      // 128 rows * 144 B
#define ST6B  (2 * A6_B)
#define MM_SMEM6 (MM6_STG * ST6B)        // 110592 B

template <int MODE>
__global__ __launch_bounds__(256, 2) void k_mm6(
    const __half* __restrict__ A, const __half* __restrict__ B,
    void* __restrict__ Cout, __half* __restrict__ cat2,
    int M, int N, int K, int tiles_m, int tiles_n,
    const float* __restrict__ xres, const float* __restrict__ temb)
{
    extern __shared__ float smf[];

    int pid = blockIdx.x;
    const int GROUPM = 16;
    int npg     = GROUPM * tiles_n;
    int groupid = pid / npg;
    int firstm  = groupid * GROUPM;
    int gsz     = min(GROUPM, tiles_m - firstm);
    int pm      = firstm + (pid % npg) % gsz;
    int pn      = (pid % npg) / gsz;
    int bm = pm * 128, bn = pn * 128;

    int tid  = threadIdx.x;
    int warp = tid >> 5, lane = tid & 31;
    int wm = warp & 1, wn = warp >> 1;
    int gid = lane >> 2, tid4 = lane & 3;

    float acc[4][4][4];
    #pragma unroll
    for (int i = 0; i < 4; i++)
        #pragma unroll
        for (int j = 0; j < 4; j++)
            #pragma unroll
            for (int q = 0; q < 4; q++) acc[i][j][q] = 0.f;

    uint32_t smb = (uint32_t)__cvta_generic_to_shared(smf);
    const __half* Ag = A + (size_t)bm * K;
    const __half* Bg = B + (size_t)bn * K;

    uint32_t aoff[4], boff[2];
    #pragma unroll
    for (int mt = 0; mt < 4; mt++)
        aoff[mt] = (uint32_t)((wm * 64 + mt * 16 + (lane & 15)) * 144 + (lane >> 4) * 16);
    #pragma unroll
    for (int p = 0; p < 2; p++)
        boff[p] = (uint32_t)A6_B
                + (uint32_t)((wn * 32 + p * 16 + ((lane >> 4) * 8) + (lane & 7)) * 144
                             + (((lane >> 3) & 1) * 16));

    #define MM6_LOAD(KB, SS)                                                    \
    {                                                                           \
        int kt_ = (KB) * 64;                                                    \
        uint32_t sa_ = smb + (uint32_t)((SS) * ST6B);                           \
        uint32_t sb_ = sa_ + (uint32_t)A6_B;                                    \
        _Pragma("unroll")                                                       \
        for (int i_ = 0; i_ < 4; i_++) {                                        \
            int id_ = tid + i_ * 256;                                           \
            int r_ = id_ >> 3, c_ = id_ & 7;                                    \
            cp16(sa_ + (uint32_t)(r_ * 144 + c_ * 16),                          \
                 Ag + (size_t)r_ * K + kt_ + c_ * 8);                           \
            cp16(sb_ + (uint32_t)(r_ * 144 + c_ * 16),                          \
                 Bg + (size_t)r_ * K + kt_ + c_ * 8);                           \
        }                                                                       \
        asm volatile("cp.async.commit_group;\n");                               \
    }

    int ntiles = K >> 6;

    MM6_LOAD(0, 0)
    MM6_LOAD(1, 1)

    int st = 0, sl = 2;
    for (int t = 0; t < ntiles; t++) {
        if (t < ntiles - 2) {
            asm volatile("cp.async.wait_group 1;\n");
        } else {
            asm volatile("cp.async.wait_group 0;\n");
        }
        __syncthreads();
        if (t + 2 < ntiles) {
            MM6_LOAD(t + 2, sl)
            sl = (sl == 2) ? 0 : sl + 1;
        }

        uint32_t sbase = smb + (uint32_t)(st * ST6B);
        st = (st == 2) ? 0 : st + 1;

        #pragma unroll
        for (int k16 = 0; k16 < 4; k16++) {
            uint32_t kb = (uint32_t)(k16 * 32);
            uint32_t af[4][4], bq0[4], bq1[4];
            #pragma unroll
            for (int mt = 0; mt < 4; mt++)
                ldsm4(af[mt], sbase + aoff[mt] + kb);
            ldsm4(bq0, sbase + boff[0] + kb);
            ldsm4(bq1, sbase + boff[1] + kb);

            #pragma unroll
            for (int mt = 0; mt < 4; mt++) {
                mma_f16(acc[mt][0], af[mt][0], af[mt][1], af[mt][2], af[mt][3], bq0[0], bq0[1]);
                mma_f16(acc[mt][1], af[mt][0], af[mt][1], af[mt][2], af[mt][3], bq0[2], bq0[3]);
                mma_f16(acc[mt][2], af[mt][0], af[mt][1], af[mt][2], af[mt][3], bq1[0], bq1[1]);
                mma_f16(acc[mt][3], af[mt][0], af[mt][1], af[mt][2], af[mt][3], bq1[2], bq1[3]);
            }
        }
    }

    __syncthreads();

    // epilogue
    bool mlp = (MODE == 1) && (bn >= QKV);
    #pragma unroll
    for (int mt = 0; mt < 4; mt++) {
        int r0 = bm + wm * 64 + mt * 16 + gid;
        #pragma unroll
        for (int nt = 0; nt < 4; nt++) {
            int c0 = bn + wn * 32 + nt * 8 + tid4 * 2;
            float2 v0 = make_float2(acc[mt][nt][0], acc[mt][nt][1]);
            float2 v1 = make_float2(acc[mt][nt][2], acc[mt][nt][3]);
            if (MODE == 2) {
                float gx = temb[2 * DIM + c0], gy = temb[2 * DIM + c0 + 1];
                float2 x0 = *(const float2*)(xres + (size_t)r0 * N + c0);
                float2 x1 = *(const float2*)(xres + (size_t)(r0 + 8) * N + c0);
                v0.x = x0.x + gx * v0.x; v0.y = x0.y + gy * v0.y;
                v1.x = x1.x + gx * v1.x; v1.y = x1.y + gy * v1.y;
                *(float2*)((float*)Cout + (size_t)r0 * N + c0)       = v0;
                *(float2*)((float*)Cout + (size_t)(r0 + 8) * N + c0) = v1;
            } else if (mlp) {
                // (v.x, v.y) = (gate_j, up_j); j = (c0 - QKV)/2
                int j = (c0 - QKV) >> 1;
                float s0 = (v0.x / (1.f + __expf(-v0.x))) * v0.y;
                float s1 = (v1.x / (1.f + __expf(-v1.x))) * v1.y;
                cat2[(size_t)r0 * CATK + DIM + j]       = __float2half_rn(s0);
                cat2[(size_t)(r0 + 8) * CATK + DIM + j] = __float2half_rn(s1);
            } else {
                *(__half2*)((__half*)Cout + (size_t)r0 * N + c0) =
                    __floats2half2_rn(v0.x, v0.y);
                *(__half2*)((__half*)Cout + (size_t)(r0 + 8) * N + c0) =
                    __floats2half2_rn(v1.x, v1.y);
            }
        }
    }
}

// ---------------- kernel 3: QKV extract + RMSNorm + RoPE (-> half Q,K) ------
__global__ __launch_bounds__(128) void k_qkvprep(
    const __half* __restrict__ P, const float* __restrict__ cosb,
    const float* __restrict__ sinb, const float* __restrict__ nqw,
    const float* __restrict__ nkw,
    __half* __restrict__ Qb, __half* __restrict__ Kb)
{
    int s = blockIdx.x, h = blockIdx.y, d = threadIdx.x;
    const __half* row = P + (size_t)s * FOUT + h * HD;
    float q = __half2float(row[d]);
    float k = __half2float(row[DIM + d]);

    __shared__ float sQ[HD], sK[HD], sred[8];
    float sq = q * q, sk = k * k;
    #pragma unroll
    for (int o = 16; o; o >>= 1) {
        sq += __shfl_xor_sync(0xffffffffu, sq, o);
        sk += __shfl_xor_sync(0xffffffffu, sk, o);
    }
    int w = d >> 5;
    if ((d & 31) == 0) { sred[w] = sq; sred[4 + w] = sk; }
    __syncthreads();
    float ssq = sred[0] + sred[1] + sred[2] + sred[3];
    float ssk = sred[4] + sred[5] + sred[6] + sred[7];
    float qn = q * rsqrtf(ssq * (1.0f / HD) + EPS) * nqw[d];
    float kn = k * rsqrtf(ssk * (1.0f / HD) + EPS) * nkw[d];
    sQ[d] = qn; sK[d] = kn;
    __syncthreads();
    float qrot = (d & 1) ? sQ[d - 1] : -sQ[d + 1];
    float krot = (d & 1) ? sK[d - 1] : -sK[d + 1];
    float c  = cosb[(size_t)s * HD + d];
    float sn = sinb[(size_t)s * HD + d];
    const float scale = 0.08838834764831843f;
    size_t o = ((size_t)h * S_LEN + s) * HD + d;
    Qb[o] = __float2half_rn((qn * c + qrot * sn) * scale);
    Kb[o] = __float2half_rn(kn * c + krot * sn);
}

// ---------------- kernel 3b: V transpose (half [S][DIM] slice -> [DIM][S]) ---
__global__ __launch_bounds__(256) void k_vT(
    const __half* __restrict__ P, __half* __restrict__ Vt)
{
    __shared__ __half t[32][34];
    int c0 = blockIdx.x * 32, s0 = blockIdx.y * 32;
    int tx = threadIdx.x & 31, ty = threadIdx.x >> 5;
    #pragma unroll
    for (int i = 0; i < 32; i += 8)
        t[ty + i][tx] = P[(size_t)(s0 + ty + i) * FOUT + 2 * DIM + c0 + tx];
    __syncthreads();
    #pragma unroll
    for (int i = 0; i < 32; i += 8)
        Vt[(size_t)(c0 + ty + i) * S_LEN + s0 + tx] = t[tx][ty + i];
}

// ---------------- kernel 4: fp16 flash attention (ldmatrix, 3-stage) --------
#define K_STRH 136
#define V_STRH 72
#define P_STRH 72
#define K_STGH (64 * K_STRH)
#define V_STGH (128 * V_STRH)
#define PW_H   (16 * P_STRH)
#define ATT_STG 3
#define ATTN_SMEM ((ATT_STG * (K_STGH + V_STGH) + 8 * PW_H) * 2)   // 125952 B

__global__ __launch_bounds__(256, 1) void k_attn3(
    const __half* __restrict__ Qb, const __half* __restrict__ Kb,
    const __half* __restrict__ Vt, __half* __restrict__ attnout)
{
    extern __shared__ __half smh[];
    __half* Ps = smh + ATT_STG * (K_STGH + V_STGH);

    int h  = blockIdx.y;
    int q0 = blockIdx.x * 128;
    int tid = threadIdx.x, warp = tid >> 5, lane = tid & 31;
    int gid = lane >> 2, tid4 = lane & 3;
    __half* Pw = Ps + warp * PW_H;
    uint32_t smbase = (uint32_t)__cvta_generic_to_shared(smh);
    uint32_t pwbase = smbase + (uint32_t)(ATT_STG * (K_STGH + V_STGH) + warp * PW_H) * 2u;

    uint32_t kfoff = (uint32_t)((((lane >> 4) * 8) + (lane & 7)) * (K_STRH * 2)
                                + ((lane >> 3) & 1) * 16);
    uint32_t vfoff = (uint32_t)((((lane >> 4) * 8) + (lane & 7)) * (V_STRH * 2)
                                + ((lane >> 3) & 1) * 16);
    uint32_t pfoff = (uint32_t)((lane & 15) * (P_STRH * 2) + (lane >> 4) * 16);

    const __half* Qg = Qb + ((size_t)h * S_LEN + q0) * HD;
    #pragma unroll
    for (int i = 0; i < 8; i++) {
        int idx = tid + i * 256;
        int r = idx >> 4, c = idx & 15;
        cp16(smbase + (uint32_t)(r * K_STRH + c * 8) * 2u, Qg + (size_t)r * HD + c * 8);
    }
    asm volatile("cp.async.commit_group;\ncp.async.wait_group 0;\n");
    __syncthreads();
    uint32_t qf[8][4];
    {
        uint32_t qoff = smbase + (uint32_t)((warp * 16 + (lane & 15)) * (K_STRH * 2)
                                            + (lane >> 4) * 16);
        #pragma unroll
        for (int k16 = 0; k16 < 8; k16++)
            ldsm4(qf[k16], qoff + (uint32_t)(k16 * 32));
    }
    __syncthreads();

    float m0 = -1e30f, m1 = -1e30f, l0 = 0.f, l1 = 0.f;
    float o[16][4];
    #pragma unroll
    for (int dt = 0; dt < 16; dt++)
        #pragma unroll
        for (int j = 0; j < 4; j++) o[dt][j] = 0.f;

    #define LOAD_KV3(T, SS)                                                       \
    {                                                                             \
        const __half* Kg = Kb + ((size_t)h * S_LEN + (T) * 64) * HD;              \
        const __half* Vg = Vt + (size_t)h * HD * S_LEN + (T) * 64;                \
        uint32_t ks = smbase + (uint32_t)((SS) * (K_STGH + V_STGH)) * 2u;         \
        uint32_t vs = ks + (uint32_t)K_STGH * 2u;                                 \
        _Pragma("unroll")                                                         \
        for (int i = 0; i < 4; i++) {                                             \
            int idx = tid + i * 256;                                              \
            int kr = idx >> 4, kc = idx & 15;                                     \
            cp16(ks + (uint32_t)(kr * K_STRH + kc * 8) * 2u,                      \
                 Kg + (size_t)kr * HD + kc * 8);                                  \
            int vr = idx >> 3, vc = idx & 7;                                      \
            cp16(vs + (uint32_t)(vr * V_STRH + vc * 8) * 2u,                      \
                 Vg + (size_t)vr * S_LEN + vc * 8);                               \
        }                                                                         \
        asm volatile("cp.async.commit_group;\n");                                 \
    }

    LOAD_KV3(0, 0)
    LOAD_KV3(1, 1)

    int st = 0, sl = 2;
    for (int t = 0; t < 64; t++) {
        if (t < 62) {
            asm volatile("cp.async.wait_group 1;\n");
        } else {
            asm volatile("cp.async.wait_group 0;\n");
        }
        __syncthreads();
        if (t + 2 < 64) {
            LOAD_KV3(t + 2, sl)
            sl = (sl == 2) ? 0 : sl + 1;
        }

        uint32_t ksb = smbase + (uint32_t)(st * (K_STGH + V_STGH)) * 2u;
        uint32_t vsb = ksb + (uint32_t)K_STGH * 2u;
        st = (st == 2) ? 0 : st + 1;

        float sa[8][4];
        #pragma unroll
        for (int nt = 0; nt < 8; nt++)
            #pragma unroll
            for (int j = 0; j < 4; j++) sa[nt][j] = 0.f;
        #pragma unroll
        for (int ntp = 0; ntp < 4; ntp++) {
            uint32_t ka = ksb + kfoff + (uint32_t)(ntp * 16 * K_STRH * 2);
            #pragma unroll
            for (int k16 = 0; k16 < 8; k16++) {
                uint32_t bq[4];
                ldsm4(bq, ka + (uint32_t)(k16 * 32));
                mma_f16(sa[2 * ntp],     qf[k16][0], qf[k16][1], qf[k16][2], qf[k16][3],
                        bq[0], bq[1]);
                mma_f16(sa[2 * ntp + 1], qf[k16][0], qf[k16][1], qf[k16][2], qf[k16][3],
                        bq[2], bq[3]);
            }
        }

        float mx0 = -1e30f, mx1 = -1e30f;
        #pragma unroll
        for (int nt = 0; nt < 8; nt++) {
            mx0 = fmaxf(mx0, fmaxf(sa[nt][0], sa[nt][1]));
            mx1 = fmaxf(mx1, fmaxf(sa[nt][2], sa[nt][3]));
        }
        mx0 = fmaxf(mx0, __shfl_xor_sync(0xffffffffu, mx0, 1));
        mx0 = fmaxf(mx0, __shfl_xor_sync(0xffffffffu, mx0, 2));
        mx1 = fmaxf(mx1, __shfl_xor_sync(0xffffffffu, mx1, 1));
        mx1 = fmaxf(mx1, __shfl_xor_sync(0xffffffffu, mx1, 2));
        float nm0 = fmaxf(m0, mx0), nm1 = fmaxf(m1, mx1);
        float corr0 = __expf(m0 - nm0), corr1 = __expf(m1 - nm1);
        float rs0 = 0.f, rs1 = 0.f;
        #pragma unroll
        for (int nt = 0; nt < 8; nt++) {
            float p0 = __expf(sa[nt][0] - nm0);
            float p1 = __expf(sa[nt][1] - nm0);
            float p2 = __expf(sa[nt][2] - nm1);
            float p3 = __expf(sa[nt][3] - nm1);
            rs0 += p0 + p1; rs1 += p2 + p3;
            *(__half2*)&Pw[gid * P_STRH + nt * 8 + 2 * tid4]       = __floats2half2_rn(p0, p1);
            *(__half2*)&Pw[(gid + 8) * P_STRH + nt * 8 + 2 * tid4] = __floats2half2_rn(p2, p3);
        }
        rs0 += __shfl_xor_sync(0xffffffffu, rs0, 1);
        rs0 += __shfl_xor_sync(0xffffffffu, rs0, 2);
        rs1 += __shfl_xor_sync(0xffffffffu, rs1, 1);
        rs1 += __shfl_xor_sync(0xffffffffu, rs1, 2);
        l0 = l0 * corr0 + rs0;
        l1 = l1 * corr1 + rs1;
        m0 = nm0; m1 = nm1;
        #pragma unroll
        for (int dt = 0; dt < 16; dt++) {
            o[dt][0] *= corr0; o[dt][1] *= corr0;
            o[dt][2] *= corr1; o[dt][3] *= corr1;
        }
        __syncwarp();

        #pragma unroll
        for (int k16 = 0; k16 < 4; k16++) {
            uint32_t aq[4];
            ldsm4(aq, pwbase + pfoff + (uint32_t)(k16 * 32));
            #pragma unroll
            for (int dtp = 0; dtp < 8; dtp++) {
                uint32_t bq[4];
                ldsm4(bq, vsb + vfoff + (uint32_t)(dtp * 16 * V_STRH * 2 + k16 * 32));
                mma_f16(o[2 * dtp],     aq[0], aq[1], aq[2], aq[3], bq[0], bq[1]);
                mma_f16(o[2 * dtp + 1], aq[0], aq[1], aq[2], aq[3], bq[2], bq[3]);
            }
        }
        __syncwarp();
    }

    float inv0 = 1.0f / l0, inv1 = 1.0f / l1;
    int r0 = q0 + warp * 16 + gid;
    #pragma unroll
    for (int dt = 0; dt < 16; dt++) {
        int col = h * HD + dt * 8 + 2 * tid4;
        *(__half2*)&attnout[(size_t)r0 * CATK + col] =
            __floats2half2_rn(o[dt][0] * inv0, o[dt][1] * inv0);
        *(__half2*)&attnout[(size_t)(r0 + 8) * CATK + col] =
            __floats2half2_rn(o[dt][2] * inv1, o[dt][3] * inv1);
    }
}

// ---------------- launch -----------------------------------------------------
extern "C" void kernel_launch(void* const* d_in, const int* in_sizes, int n_in,
                              void* d_out, int out_size)
{
    const float* x       = (const float*)d_in[0];
    const float* temb    = (const float*)d_in[1];
    const float* rcos    = (const float*)d_in[2];
    const float* rsin    = (const float*)d_in[3];
    const float* w1      = (const float*)d_in[4];
    const float* wo_attn = (const float*)d_in[5];
    const float* wo_mlp  = (const float*)d_in[6];
    const float* nqw     = (const float*)d_in[7];
    const float* nkw     = (const float*)d_in[8];
    float* out = (float*)d_out;

    __half *h, *P, *Qb, *Kb, *Vt, *cat, *w1h, *woh;
    cudaGetSymbolAddress((void**)&h,   g_h);
    cudaGetSymbolAddress((void**)&P,   g_P);
    cudaGetSymbolAddress((void**)&Qb,  g_Qb);
    cudaGetSymbolAddress((void**)&Kb,  g_Kb);
    cudaGetSymbolAddress((void**)&Vt,  g_Vt);
    cudaGetSymbolAddress((void**)&cat, g_cat);
    cudaGetSymbolAddress((void**)&w1h, g_w1h);
    cudaGetSymbolAddress((void**)&woh, g_woh);

    // 0) weight convert + transpose to half [row][K]
    //    w1 QKV columns -> rows 0..QKV-1; MLP gate/up interleaved rows QKV+2j / QKV+2j+1
    k_cvtT<<<dim3(QKV / 32, DIM / 32), 256>>>(w1,             w1h, FOUT, DIM,  0,   0,       1);
    k_cvtT<<<dim3(MH  / 32, DIM / 32), 256>>>(w1 + QKV,       w1h, FOUT, DIM,  0,   QKV,     2);
    k_cvtT<<<dim3(MH  / 32, DIM / 32), 256>>>(w1 + QKV + MH,  w1h, FOUT, DIM,  0,   QKV + 1, 2);
    k_cvtT<<<dim3(DIM / 32, DIM / 32), 256>>>(wo_attn,        woh, DIM,  CATK, 0,   0,       1);
    k_cvtT<<<dim3(DIM / 32, MH  / 32), 256>>>(wo_mlp,         woh, DIM,  CATK, DIM, 0,       1);

    // 1) LayerNorm + modulation -> half h
    k_lnmod<<<S_LEN, 256>>>(x, temb, h);

    cudaFuncSetAttribute((const void*)k_mm6<1>,
                         cudaFuncAttributeMaxDynamicSharedMemorySize, MM_SMEM6);
    cudaFuncSetAttribute((const void*)k_mm6<2>,
                         cudaFuncAttributeMaxDynamicSharedMemorySize, MM_SMEM6);

    // 2) fused QKV+MLP projection; MLP part feeds swiglu directly into cat
    {
        int tm = S_LEN / 128, tn = FOUT / 128;
        k_mm6<1><<<tm * tn, 256, MM_SMEM6>>>(
            h, w1h, P, cat, S_LEN, FOUT, DIM, tm, tn, nullptr, nullptr);
    }

    // 3) Q/K heads + RMSNorm + RoPE (half); 3b) V transpose
    {
        dim3 g(S_LEN, HEADS);
        k_qkvprep<<<g, 128>>>(P, rcos, rsin, nqw, nkw, Qb, Kb);
        k_vT<<<dim3(DIM / 32, S_LEN / 32), 256>>>(P, Vt);
    }

    // 4) fp16 attention -> cat[:, 0:3072]
    {
        cudaFuncSetAttribute(k_attn3, cudaFuncAttributeMaxDynamicSharedMemorySize, ATTN_SMEM);
        dim3 g(S_LEN / 128, HEADS);
        k_attn3<<<g, 256, ATTN_SMEM>>>(Qb, Kb, Vt, cat);
    }

    // 5) out = x + gate * (cat @ [wo_attn ; wo_mlp])   (K = 12288)
    {
        int tm = S_LEN / 128, tn = DIM / 128;
        k_mm6<2><<<tm * tn, 256, MM_SMEM6>>>(
            cat, woh, out, cat, S_LEN, DIM, CATK, tm, tn, x, temb);
    }
}